// round 9
// baseline (speedup 1.0000x reference)
#include <cuda_runtime.h>
#include <cuda_bf16.h>
#include <cstddef>
#include <cstdint>

#define N_NODES_MAX 50000
#define E_MAX       800000
#define IN_CH   128
#define HID_CH  256
#define OUT_CH  128
#define BN_EPS  1e-5f
#define SA      144      // smem row stride (bytes): 64 bf16 + 16B pad

// ---------------- scratch (device globals) ----------------
__device__ float g_y1[(size_t)N_NODES_MAX * HID_CH];   // gemm1 output
__device__ float g_zx[(size_t)N_NODES_MAX * IN_CH];    // agg(x); later reused as h2
__device__ int   g_degi[N_NODES_MAX];
__device__ int   g_off[N_NODES_MAX];                   // scan; post-fill: row END offsets
__device__ int   g_esrc[E_MAX];
__device__ int   g_bsum[256];
__device__ int   g_bscan[256];
__device__ float g_dis[N_NODES_MAX];
__device__ float g_bnsum[HID_CH];
__device__ float g_bnsq[HID_CH];
__device__ float g_scale[HID_CH];
__device__ float g_shift[HID_CH];
// W transposed + split to bf16 (K-major rows: [N][K])
__device__ __align__(16) __nv_bfloat16 g_wt1hi[HID_CH * IN_CH];   // [256,128]
__device__ __align__(16) __nv_bfloat16 g_wt1lo[HID_CH * IN_CH];
__device__ __align__(16) __nv_bfloat16 g_wt2hi[OUT_CH * HID_CH];  // [128,256]
__device__ __align__(16) __nv_bfloat16 g_wt2lo[OUT_CH * HID_CH];

__device__ __forceinline__ void fma4(float4& a, const float4 v, const float s) {
    a.x = fmaf(v.x, s, a.x);
    a.y = fmaf(v.y, s, a.y);
    a.z = fmaf(v.z, s, a.z);
    a.w = fmaf(v.w, s, a.w);
}

__device__ __forceinline__ uint32_t smem_u32(const void* p) {
    uint32_t a;
    asm("{ .reg .u64 t; cvta.to.shared.u64 t, %1; cvt.u32.u64 %0, t; }" : "=r"(a) : "l"(p));
    return a;
}

#define LDSM_X4(r, addr) \
    asm volatile("ldmatrix.sync.aligned.m8n8.x4.shared.b16 {%0,%1,%2,%3}, [%4];" \
                 : "=r"((r)[0]), "=r"((r)[1]), "=r"((r)[2]), "=r"((r)[3]) : "r"(addr))

__device__ __forceinline__ void mma16816(float* c, const uint32_t* a, uint32_t b0, uint32_t b1) {
    asm volatile(
        "mma.sync.aligned.m16n8k16.row.col.f32.bf16.bf16.f32 "
        "{%0,%1,%2,%3}, {%4,%5,%6,%7}, {%8,%9}, {%0,%1,%2,%3};"
        : "+f"(c[0]), "+f"(c[1]), "+f"(c[2]), "+f"(c[3])
        : "r"(a[0]), "r"(a[1]), "r"(a[2]), "r"(a[3]), "r"(b0), "r"(b1));
}

// ---------------- init + W transpose/split (fused) ----------------
__global__ void k_initprep(const float* __restrict__ W1, const float* __restrict__ W2, int M) {
    int i = blockIdx.x * blockDim.x + threadIdx.x;   // 65536 threads
    if (i < M) g_degi[i] = 0;
    if (i < HID_CH) { g_bnsum[i] = 0.f; g_bnsq[i] = 0.f; }
    if (i < IN_CH * HID_CH) {                 // W1 [128,256] -> WT1 [256,128]
        int k = i / HID_CH, n = i % HID_CH;
        float v = W1[i];
        __nv_bfloat16 h = __float2bfloat16(v);
        g_wt1hi[n * IN_CH + k] = h;
        g_wt1lo[n * IN_CH + k] = __float2bfloat16(v - __bfloat162float(h));
    }
    if (i < HID_CH * OUT_CH) {                // W2 [256,128] -> WT2 [128,256]
        int k = i / OUT_CH, n = i % OUT_CH;
        float v = W2[i];
        __nv_bfloat16 h = __float2bfloat16(v);
        g_wt2hi[n * HID_CH + k] = h;
        g_wt2lo[n * HID_CH + k] = __float2bfloat16(v - __bfloat162float(h));
    }
}

// ---------------- degree histogram ----------------
__global__ void k_deg(const int* __restrict__ dst, int E) {
    int i = blockIdx.x * blockDim.x + threadIdx.x;
    if (i < E) atomicAdd(&g_degi[dst[i]], 1);
}

// ---------------- exclusive scan over degrees ----------------
__global__ void k_scan1(int M) {
    __shared__ int s[256];
    int tid = threadIdx.x;
    int i = blockIdx.x * 256 + tid;
    int v = (i < M) ? g_degi[i] : 0;
    s[tid] = v;
    __syncthreads();
#pragma unroll
    for (int off = 1; off < 256; off <<= 1) {
        int t = (tid >= off) ? s[tid - off] : 0;
        __syncthreads();
        s[tid] += t;
        __syncthreads();
    }
    if (i < M) g_off[i] = s[tid] - v;
    if (tid == 255) g_bsum[blockIdx.x] = s[255];
}

__global__ void k_scan2(int NB) {
    __shared__ int s[256];
    int tid = threadIdx.x;
    int v = (tid < NB) ? g_bsum[tid] : 0;
    s[tid] = v;
    __syncthreads();
#pragma unroll
    for (int off = 1; off < 256; off <<= 1) {
        int t = (tid >= off) ? s[tid - off] : 0;
        __syncthreads();
        s[tid] += t;
        __syncthreads();
    }
    g_bscan[tid] = s[tid] - v;
}

// scan finalize + dis (fused)
__global__ void k_scan3_dis(int M) {
    int i = blockIdx.x * blockDim.x + threadIdx.x;
    if (i < M) {
        g_off[i] += g_bscan[i >> 8];
        g_dis[i] = rsqrtf((float)g_degi[i] + 1.0f);
    }
}

// ---------------- CSR fill (cursor = g_off itself; post-fill g_off[d] = row end) ----------------
__global__ void k_fill(const int* __restrict__ src, const int* __restrict__ dst, int E) {
    int i = blockIdx.x * blockDim.x + threadIdx.x;
    if (i < E) {
        int d = dst[i];
        int pos = atomicAdd(&g_off[d], 1);
        g_esrc[pos] = src[i];
    }
}

// ---------------- 128-ch gather, 8-edge unroll + dual accumulators ----------------
// outp[d] = sum_in inp[s]*norm + inp[d]*dis^2 (+bias)
// CSR rows: [d ? g_off[d-1] : 0, g_off[d])
template <bool BIAS>
__global__ __launch_bounds__(256) void k_gather(const float* __restrict__ inp,
                                                float* __restrict__ outp,
                                                const float* __restrict__ bias,
                                                int M, int E) {
    const int tid = threadIdx.x, lane = tid & 31, wid = tid >> 5;
    float4 bb = make_float4(0.f, 0.f, 0.f, 0.f);
    if (BIAS) bb = ((const float4*)bias)[lane];

    for (int d = blockIdx.x * 8 + wid; d < M; d += gridDim.x * 8) {
        float disd = g_dis[d];
        int beg = d ? g_off[d - 1] : 0;
        int end = g_off[d];
        float4 a  = make_float4(0.f, 0.f, 0.f, 0.f);
        float4 a2 = make_float4(0.f, 0.f, 0.f, 0.f);

        int j = beg;
        for (; j + 8 <= end; j += 8) {
            int s0 = g_esrc[j],     s1 = g_esrc[j + 1];
            int s2 = g_esrc[j + 2], s3 = g_esrc[j + 3];
            int s4 = g_esrc[j + 4], s5 = g_esrc[j + 5];
            int s6 = g_esrc[j + 6], s7 = g_esrc[j + 7];
            float w0 = g_dis[s0], w1 = g_dis[s1], w2 = g_dis[s2], w3 = g_dis[s3];
            float w4 = g_dis[s4], w5 = g_dis[s5], w6 = g_dis[s6], w7 = g_dis[s7];
            float4 v0 = ((const float4*)(inp + (size_t)s0 * 128))[lane];
            float4 v1 = ((const float4*)(inp + (size_t)s1 * 128))[lane];
            float4 v2 = ((const float4*)(inp + (size_t)s2 * 128))[lane];
            float4 v3 = ((const float4*)(inp + (size_t)s3 * 128))[lane];
            float4 v4 = ((const float4*)(inp + (size_t)s4 * 128))[lane];
            float4 v5 = ((const float4*)(inp + (size_t)s5 * 128))[lane];
            float4 v6 = ((const float4*)(inp + (size_t)s6 * 128))[lane];
            float4 v7 = ((const float4*)(inp + (size_t)s7 * 128))[lane];
            fma4(a,  v0, disd * w0);
            fma4(a2, v1, disd * w1);
            fma4(a,  v2, disd * w2);
            fma4(a2, v3, disd * w3);
            fma4(a,  v4, disd * w4);
            fma4(a2, v5, disd * w5);
            fma4(a,  v6, disd * w6);
            fma4(a2, v7, disd * w7);
        }
        for (; j + 2 <= end; j += 2) {
            int s0 = g_esrc[j], s1 = g_esrc[j + 1];
            float w0 = g_dis[s0], w1 = g_dis[s1];
            float4 v0 = ((const float4*)(inp + (size_t)s0 * 128))[lane];
            float4 v1 = ((const float4*)(inp + (size_t)s1 * 128))[lane];
            fma4(a,  v0, disd * w0);
            fma4(a2, v1, disd * w1);
        }
        if (j < end) {
            int s0 = g_esrc[j];
            float w0 = disd * g_dis[s0];
            float4 v0 = ((const float4*)(inp + (size_t)s0 * 128))[lane];
            fma4(a, v0, w0);
        }
        float self = disd * disd;
        float4 sv = ((const float4*)(inp + (size_t)d * 128))[lane];
        fma4(a, sv, self);
        a.x += a2.x; a.y += a2.y; a.z += a2.z; a.w += a2.w;
        if (BIAS) { a.x += bb.x; a.y += bb.y; a.z += bb.z; a.w += bb.w; }
        ((float4*)(outp + (size_t)d * 128))[lane] = a;
    }
}

// ---------------- mma.sync bf16-split GEMM ----------------
// C[M,NTOT] = op(A)[M,KTOT] @ W[KTOT,NTOT]; W pre-split: Bhi/Blo [NTOT][KTOT] bf16.
// BN_A fuses relu(a*scale+shift) into A convert; BIASF adds bias[col] in epilogue;
// BNSTATS accumulates per-column sum/sumsq of C (rows < M only) into g_bnsum/g_bnsq.
template <bool BN_A, bool BIASF, bool BNSTATS, int KTOT, int NTOT, int BM>
__global__ __launch_bounds__(256, 2)
void k_mma_gemm(const float* __restrict__ A,
                const __nv_bfloat16* __restrict__ Bhi,
                const __nv_bfloat16* __restrict__ Blo,
                const float* __restrict__ bias,
                float* __restrict__ C, int M) {
    constexpr int KC = 64;
    constexpr int NCH = KTOT / KC;
    constexpr int WARPS_M = BM / 32;
    constexpr int WARPS_N = 8 / WARPS_M;
    constexpr int WN = 128 / WARPS_N;
    constexpr int NT16 = WN / 16;
    constexpr int N8 = WN / 8;
    constexpr int AITER = BM * 16 / 256;

    extern __shared__ char sm[];
    char* Ah = sm;
    char* Al = Ah + BM * SA;
    char* Bh = Al + BM * SA;
    char* Bl = Bh + 128 * SA;
    __shared__ float s_sum[128], s_sq[128];

    const int tid  = threadIdx.x;
    const int lane = tid & 31;
    const int wid  = tid >> 5;
    const int warpM = wid % WARPS_M;
    const int warpN = wid / WARPS_M;
    const int rowBase = blockIdx.y * BM;
    const int colBase = blockIdx.x * 128;

    if (BNSTATS && tid < 128) { s_sum[tid] = 0.f; s_sq[tid] = 0.f; }

    float acc[2][N8][4];
#pragma unroll
    for (int i = 0; i < 2; i++)
#pragma unroll
        for (int j = 0; j < N8; j++)
#pragma unroll
            for (int q = 0; q < 4; q++) acc[i][j][q] = 0.f;

    const uint32_t sAh = smem_u32(Ah), sAl = smem_u32(Al);
    const uint32_t sBh = smem_u32(Bh), sBl = smem_u32(Bl);

    for (int ck = 0; ck < NCH; ck++) {
#pragma unroll
        for (int i = 0; i < AITER; i++) {
            int f = tid + i * 256;
            int r = f >> 4;
            int kq = f & 15;
            int grow = rowBase + r;
            float4 v = make_float4(0.f, 0.f, 0.f, 0.f);
            if (grow < M) {
                v = *(const float4*)(A + (size_t)grow * KTOT + ck * KC + kq * 4);
                if (BN_A) {
                    const float4 sc = *(const float4*)(g_scale + ck * KC + kq * 4);
                    const float4 sh = *(const float4*)(g_shift + ck * KC + kq * 4);
                    v.x = fmaxf(fmaf(v.x, sc.x, sh.x), 0.f);
                    v.y = fmaxf(fmaf(v.y, sc.y, sh.y), 0.f);
                    v.z = fmaxf(fmaf(v.z, sc.z, sh.z), 0.f);
                    v.w = fmaxf(fmaf(v.w, sc.w, sh.w), 0.f);
                }
            }
            __nv_bfloat162 h01 = __nv_bfloat162(__float2bfloat16(v.x), __float2bfloat16(v.y));
            __nv_bfloat162 h23 = __nv_bfloat162(__float2bfloat16(v.z), __float2bfloat16(v.w));
            __nv_bfloat162 l01 = __nv_bfloat162(
                __float2bfloat16(v.x - __bfloat162float(h01.x)),
                __float2bfloat16(v.y - __bfloat162float(h01.y)));
            __nv_bfloat162 l23 = __nv_bfloat162(
                __float2bfloat16(v.z - __bfloat162float(h23.x)),
                __float2bfloat16(v.w - __bfloat162float(h23.y)));
            uint32_t o = (uint32_t)r * SA + (uint32_t)kq * 8;
            *(uint2*)(Ah + o) = make_uint2(*(uint32_t*)&h01, *(uint32_t*)&h23);
            *(uint2*)(Al + o) = make_uint2(*(uint32_t*)&l01, *(uint32_t*)&l23);
        }
#pragma unroll
        for (int i = 0; i < 4; i++) {
            int f = tid + i * 256;
            int r = f >> 3;
            int g = f & 7;
            size_t si = (size_t)(colBase + r) * KTOT + ck * KC + g * 8;
            uint32_t o = (uint32_t)r * SA + (uint32_t)g * 16;
            *(uint4*)(Bh + o) = *(const uint4*)(Bhi + si);
            *(uint4*)(Bl + o) = *(const uint4*)(Blo + si);
        }
        __syncthreads();

#pragma unroll
        for (int pass = 0; pass < 3; pass++) {
            const uint32_t sa = (pass == 2) ? sAl : sAh;
            const uint32_t sb = (pass == 1) ? sBl : sBh;
#pragma unroll
            for (int ks = 0; ks < KC / 16; ks++) {
                const int k0 = ks * 16;
                uint32_t af[2][4];
#pragma unroll
                for (int mt = 0; mt < 2; mt++) {
                    int row = warpM * 32 + mt * 16 + (lane & 15);
                    uint32_t addr = sa + (uint32_t)row * SA +
                                    (uint32_t)(k0 + ((lane >> 4) << 3)) * 2;
                    LDSM_X4(af[mt], addr);
                }
                uint32_t bf[NT16][4];
#pragma unroll
                for (int nt = 0; nt < NT16; nt++) {
                    int nrow = warpN * WN + nt * 16 + ((lane >> 4) << 3) + (lane & 7);
                    uint32_t addr = sb + (uint32_t)nrow * SA +
                                    (uint32_t)(k0 + (((lane >> 3) & 1) << 3)) * 2;
                    LDSM_X4(bf[nt], addr);
                }
#pragma unroll
                for (int mt = 0; mt < 2; mt++)
#pragma unroll
                    for (int j = 0; j < N8; j++)
                        mma16816(acc[mt][j], af[mt],
                                 bf[j >> 1][(j & 1) * 2], bf[j >> 1][(j & 1) * 2 + 1]);
            }
        }
        __syncthreads();
    }

    // ---- epilogue: store (+bias), optional BN-stat accumulation ----
#pragma unroll
    for (int mt = 0; mt < 2; mt++) {
        int r0 = rowBase + warpM * 32 + mt * 16 + (lane >> 2);
#pragma unroll
        for (int j = 0; j < N8; j++) {
            int colL = warpN * WN + j * 8 + (lane & 3) * 2;   // block-local col
            int col = colBase + colL;
            float b0 = 0.f, b1v = 0.f;
            if (BIASF) { b0 = __ldg(bias + col); b1v = __ldg(bias + col + 1); }
            float v0 = acc[mt][j][0] + b0, v1 = acc[mt][j][1] + b1v;
            float v2 = acc[mt][j][2] + b0, v3 = acc[mt][j][3] + b1v;
            bool ok0 = (r0 < M), ok1 = (r0 + 8 < M);
            if (ok0) *(float2*)(C + (size_t)r0 * NTOT + col) = make_float2(v0, v1);
            if (ok1) *(float2*)(C + (size_t)(r0 + 8) * NTOT + col) = make_float2(v2, v3);
            if (BNSTATS) {
                float se = (ok0 ? v0 : 0.f) + (ok1 ? v2 : 0.f);
                float so = (ok0 ? v1 : 0.f) + (ok1 ? v3 : 0.f);
                float qe = (ok0 ? v0 * v0 : 0.f) + (ok1 ? v2 * v2 : 0.f);
                float qo = (ok0 ? v1 * v1 : 0.f) + (ok1 ? v3 * v3 : 0.f);
                atomicAdd(&s_sum[colL], se);
                atomicAdd(&s_sum[colL + 1], so);
                atomicAdd(&s_sq[colL], qe);
                atomicAdd(&s_sq[colL + 1], qo);
            }
        }
    }
    if (BNSTATS) {
        __syncthreads();
        if (tid < 128) {
            atomicAdd(&g_bnsum[colBase + tid], s_sum[tid]);
            atomicAdd(&g_bnsq[colBase + tid], s_sq[tid]);
        }
    }
}

__global__ void k_bn_finalize(const float* __restrict__ gamma,
                              const float* __restrict__ beta, int M) {
    int c = threadIdx.x;
    if (c >= HID_CH) return;
    float inv = 1.0f / (float)M;
    float mu  = g_bnsum[c] * inv;
    float var = g_bnsq[c] * inv - mu * mu;
    float rs  = rsqrtf(var + BN_EPS);
    float sc  = gamma[c] * rs;
    g_scale[c] = sc;
    g_shift[c] = beta[c] - mu * sc;
}

// ---------------- launch ----------------
extern "C" void kernel_launch(void* const* d_in, const int* in_sizes, int n_in,
                              void* d_out, int out_size) {
    const float* x      = (const float*)d_in[0];
    const int*   ei     = (const int*)  d_in[1];
    const float* W1     = (const float*)d_in[2];
    const float* b1     = (const float*)d_in[3];
    const float* gamma1 = (const float*)d_in[4];
    const float* beta1  = (const float*)d_in[5];
    const float* W2     = (const float*)d_in[6];
    const float* b2     = (const float*)d_in[7];
    float* out = (float*)d_out;

    const int M = in_sizes[0] / IN_CH;    // 50000
    const int E = in_sizes[1] / 2;        // 800000
    const int* src = ei;
    const int* dst = ei + E;

    float *py1, *pzx;
    cudaGetSymbolAddress((void**)&py1, g_y1);
    cudaGetSymbolAddress((void**)&pzx, g_zx);
    __nv_bfloat16 *pw1h, *pw1l, *pw2h, *pw2l;
    cudaGetSymbolAddress((void**)&pw1h, g_wt1hi);
    cudaGetSymbolAddress((void**)&pw1l, g_wt1lo);
    cudaGetSymbolAddress((void**)&pw2h, g_wt2hi);
    cudaGetSymbolAddress((void**)&pw2l, g_wt2lo);

    const int SM1 = (128 + 128 + 128 + 128) * SA;  // BM=128: 73728 B
    const int SM2 = (64 + 64 + 128 + 128) * SA;    // BM=64:  55296 B
    cudaFuncSetAttribute(k_mma_gemm<false, true, true, IN_CH, HID_CH, 128>,
                         cudaFuncAttributeMaxDynamicSharedMemorySize, SM1);
    cudaFuncSetAttribute(k_mma_gemm<true, false, false, HID_CH, OUT_CH, 64>,
                         cudaFuncAttributeMaxDynamicSharedMemorySize, SM2);

    const int NB = (M + 255) / 256;

    // CSR build + normalization + weight prep
    k_initprep<<<256, 256>>>(W1, W2, M);
    k_deg<<<(E + 255) / 256, 256>>>(dst, E);
    k_scan1<<<NB, 256>>>(M);
    k_scan2<<<1, 256>>>(NB);
    k_scan3_dis<<<(M + 255) / 256, 256>>>(M);
    k_fill<<<(E + 255) / 256, 256>>>(src, dst, E);

    // layer 1: zx = agg(x)  (128-ch gather, 8-edge unrolled)
    k_gather<false><<<592, 256>>>(x, pzx, nullptr, M, E);
    // y1 = zx @ W1 + b1, BN stats fused into epilogue
    {
        dim3 grid(HID_CH / 128, (M + 127) / 128);
        k_mma_gemm<false, true, true, IN_CH, HID_CH, 128><<<grid, 256, SM1>>>(
            pzx, pw1h, pw1l, b1, py1, M);
    }
    k_bn_finalize<<<1, HID_CH>>>(gamma1, beta1, M);

    // layer 2: h2 = relu(bn(y1)) @ W2  (reuses g_zx for h2)
    {
        dim3 grid(OUT_CH / 128, (M + 63) / 64);
        k_mma_gemm<true, false, false, HID_CH, OUT_CH, 64><<<grid, 256, SM2>>>(
            py1, pw2h, pw2l, nullptr, pzx, M);
    }
    // out = agg(h2) + b2
    k_gather<true><<<592, 256>>>(pzx, out, b2, M, E);
}

// round 10
// speedup vs baseline: 1.3371x; 1.3371x over previous
#include <cuda_runtime.h>
#include <cuda_bf16.h>
#include <cstddef>
#include <cstdint>

#define N_NODES_MAX 50000
#define E_MAX       800000
#define IN_CH   128
#define HID_CH  256
#define OUT_CH  128
#define BN_EPS  1e-5f
#define SA      144      // smem row stride (bytes): 64 bf16 + 16B pad

// ---------------- scratch (device globals) ----------------
__device__ float g_y1[(size_t)N_NODES_MAX * HID_CH];   // gemm1 output
__device__ float g_zx[(size_t)N_NODES_MAX * IN_CH];    // agg(x); later reused as h2
__device__ int   g_degi[N_NODES_MAX];
__device__ int   g_off[N_NODES_MAX];                   // scan; post-fill: row END offsets
__device__ int   g_esrc[E_MAX];
__device__ int   g_bsum[256];
__device__ int   g_bscan[256];
__device__ float g_dis[N_NODES_MAX];
__device__ float g_bnsum[HID_CH];
__device__ float g_bnsq[HID_CH];
__device__ float g_scale[HID_CH];
__device__ float g_shift[HID_CH];
// W transposed + split to bf16 (K-major rows: [N][K])
__device__ __align__(16) __nv_bfloat16 g_wt1hi[HID_CH * IN_CH];   // [256,128]
__device__ __align__(16) __nv_bfloat16 g_wt1lo[HID_CH * IN_CH];
__device__ __align__(16) __nv_bfloat16 g_wt2hi[OUT_CH * HID_CH];  // [128,256]
__device__ __align__(16) __nv_bfloat16 g_wt2lo[OUT_CH * HID_CH];

__device__ __forceinline__ void fma4(float4& a, const float4 v, const float s) {
    a.x = fmaf(v.x, s, a.x);
    a.y = fmaf(v.y, s, a.y);
    a.z = fmaf(v.z, s, a.z);
    a.w = fmaf(v.w, s, a.w);
}

__device__ __forceinline__ uint32_t smem_u32(const void* p) {
    uint32_t a;
    asm("{ .reg .u64 t; cvta.to.shared.u64 t, %1; cvt.u32.u64 %0, t; }" : "=r"(a) : "l"(p));
    return a;
}

#define LDSM_X4(r, addr) \
    asm volatile("ldmatrix.sync.aligned.m8n8.x4.shared.b16 {%0,%1,%2,%3}, [%4];" \
                 : "=r"((r)[0]), "=r"((r)[1]), "=r"((r)[2]), "=r"((r)[3]) : "r"(addr))

__device__ __forceinline__ void mma16816(float* c, const uint32_t* a, uint32_t b0, uint32_t b1) {
    asm volatile(
        "mma.sync.aligned.m16n8k16.row.col.f32.bf16.bf16.f32 "
        "{%0,%1,%2,%3}, {%4,%5,%6,%7}, {%8,%9}, {%0,%1,%2,%3};"
        : "+f"(c[0]), "+f"(c[1]), "+f"(c[2]), "+f"(c[3])
        : "r"(a[0]), "r"(a[1]), "r"(a[2]), "r"(a[3]), "r"(b0), "r"(b1));
}

// ---------------- init + W transpose/split (fused) ----------------
__global__ void k_initprep(const float* __restrict__ W1, const float* __restrict__ W2, int M) {
    int i = blockIdx.x * blockDim.x + threadIdx.x;   // 65536 threads
    if (i < M) g_degi[i] = 0;
    if (i < HID_CH) { g_bnsum[i] = 0.f; g_bnsq[i] = 0.f; }
    if (i < IN_CH * HID_CH) {                 // W1 [128,256] -> WT1 [256,128]
        int k = i / HID_CH, n = i % HID_CH;
        float v = W1[i];
        __nv_bfloat16 h = __float2bfloat16(v);
        g_wt1hi[n * IN_CH + k] = h;
        g_wt1lo[n * IN_CH + k] = __float2bfloat16(v - __bfloat162float(h));
    }
    if (i < HID_CH * OUT_CH) {                // W2 [256,128] -> WT2 [128,256]
        int k = i / OUT_CH, n = i % OUT_CH;
        float v = W2[i];
        __nv_bfloat16 h = __float2bfloat16(v);
        g_wt2hi[n * HID_CH + k] = h;
        g_wt2lo[n * HID_CH + k] = __float2bfloat16(v - __bfloat162float(h));
    }
}

// ---------------- degree histogram ----------------
__global__ void k_deg(const int* __restrict__ dst, int E) {
    int i = blockIdx.x * blockDim.x + threadIdx.x;
    if (i < E) atomicAdd(&g_degi[dst[i]], 1);
}

// ---------------- exclusive scan over degrees ----------------
__global__ void k_scan1(int M) {
    __shared__ int s[256];
    int tid = threadIdx.x;
    int i = blockIdx.x * 256 + tid;
    int v = (i < M) ? g_degi[i] : 0;
    s[tid] = v;
    __syncthreads();
#pragma unroll
    for (int off = 1; off < 256; off <<= 1) {
        int t = (tid >= off) ? s[tid - off] : 0;
        __syncthreads();
        s[tid] += t;
        __syncthreads();
    }
    if (i < M) g_off[i] = s[tid] - v;
    if (tid == 255) g_bsum[blockIdx.x] = s[255];
}

__global__ void k_scan2(int NB) {
    __shared__ int s[256];
    int tid = threadIdx.x;
    int v = (tid < NB) ? g_bsum[tid] : 0;
    s[tid] = v;
    __syncthreads();
#pragma unroll
    for (int off = 1; off < 256; off <<= 1) {
        int t = (tid >= off) ? s[tid - off] : 0;
        __syncthreads();
        s[tid] += t;
        __syncthreads();
    }
    g_bscan[tid] = s[tid] - v;
}

// scan finalize + dis (fused)
__global__ void k_scan3_dis(int M) {
    int i = blockIdx.x * blockDim.x + threadIdx.x;
    if (i < M) {
        g_off[i] += g_bscan[i >> 8];
        g_dis[i] = rsqrtf((float)g_degi[i] + 1.0f);
    }
}

// ---------------- CSR fill (cursor = g_off itself; post-fill g_off[d] = row end) ----------------
__global__ void k_fill(const int* __restrict__ src, const int* __restrict__ dst, int E) {
    int i = blockIdx.x * blockDim.x + threadIdx.x;
    if (i < E) {
        int d = dst[i];
        int pos = atomicAdd(&g_off[d], 1);
        g_esrc[pos] = src[i];
    }
}

// ---------------- 128-ch gather, 4-edge unroll + dual accumulators (R8-proven) ----------------
// outp[d] = sum_in inp[s]*norm + inp[d]*dis^2 (+bias)
// CSR rows: [d ? g_off[d-1] : 0, g_off[d])
template <bool BIAS>
__global__ __launch_bounds__(256) void k_gather(const float* __restrict__ inp,
                                                float* __restrict__ outp,
                                                const float* __restrict__ bias,
                                                int M, int E) {
    const int tid = threadIdx.x, lane = tid & 31, wid = tid >> 5;
    float4 bb = make_float4(0.f, 0.f, 0.f, 0.f);
    if (BIAS) bb = ((const float4*)bias)[lane];

    for (int d = blockIdx.x * 8 + wid; d < M; d += gridDim.x * 8) {
        float disd = g_dis[d];
        int beg = d ? g_off[d - 1] : 0;
        int end = g_off[d];
        float4 a  = make_float4(0.f, 0.f, 0.f, 0.f);
        float4 a2 = make_float4(0.f, 0.f, 0.f, 0.f);

        int j = beg;
        for (; j + 4 <= end; j += 4) {
            int s0 = g_esrc[j],     s1 = g_esrc[j + 1];
            int s2 = g_esrc[j + 2], s3 = g_esrc[j + 3];
            float w0 = g_dis[s0], w1 = g_dis[s1], w2 = g_dis[s2], w3 = g_dis[s3];
            float4 v0 = ((const float4*)(inp + (size_t)s0 * 128))[lane];
            float4 v1 = ((const float4*)(inp + (size_t)s1 * 128))[lane];
            float4 v2 = ((const float4*)(inp + (size_t)s2 * 128))[lane];
            float4 v3 = ((const float4*)(inp + (size_t)s3 * 128))[lane];
            fma4(a,  v0, disd * w0);
            fma4(a2, v1, disd * w1);
            fma4(a,  v2, disd * w2);
            fma4(a2, v3, disd * w3);
        }
        for (; j < end; j++) {
            int s0 = g_esrc[j];
            float w0 = disd * g_dis[s0];
            float4 v0 = ((const float4*)(inp + (size_t)s0 * 128))[lane];
            fma4(a, v0, w0);
        }
        float self = disd * disd;
        float4 sv = ((const float4*)(inp + (size_t)d * 128))[lane];
        fma4(a, sv, self);
        a.x += a2.x; a.y += a2.y; a.z += a2.z; a.w += a2.w;
        if (BIAS) { a.x += bb.x; a.y += bb.y; a.z += bb.z; a.w += bb.w; }
        ((float4*)(outp + (size_t)d * 128))[lane] = a;
    }
}

// ---------------- mma.sync bf16-split GEMM (R8-proven) ----------------
// C[M,NTOT] = op(A)[M,KTOT] @ W[KTOT,NTOT]; W pre-split: Bhi/Blo [NTOT][KTOT] bf16.
// BN_A fuses relu(a*scale+shift) into the A convert; BIASF adds bias[col] in epilogue.
template <bool BN_A, bool BIASF, int KTOT, int NTOT, int BM>
__global__ __launch_bounds__(256, 2)
void k_mma_gemm(const float* __restrict__ A,
                const __nv_bfloat16* __restrict__ Bhi,
                const __nv_bfloat16* __restrict__ Blo,
                const float* __restrict__ bias,
                float* __restrict__ C, int M) {
    constexpr int KC = 64;
    constexpr int NCH = KTOT / KC;
    constexpr int WARPS_M = BM / 32;
    constexpr int WARPS_N = 8 / WARPS_M;
    constexpr int WN = 128 / WARPS_N;
    constexpr int NT16 = WN / 16;
    constexpr int N8 = WN / 8;
    constexpr int AITER = BM * 16 / 256;

    extern __shared__ char sm[];
    char* Ah = sm;
    char* Al = Ah + BM * SA;
    char* Bh = Al + BM * SA;
    char* Bl = Bh + 128 * SA;

    const int tid  = threadIdx.x;
    const int lane = tid & 31;
    const int wid  = tid >> 5;
    const int warpM = wid % WARPS_M;
    const int warpN = wid / WARPS_M;
    const int rowBase = blockIdx.y * BM;
    const int colBase = blockIdx.x * 128;

    float acc[2][N8][4];
#pragma unroll
    for (int i = 0; i < 2; i++)
#pragma unroll
        for (int j = 0; j < N8; j++)
#pragma unroll
            for (int q = 0; q < 4; q++) acc[i][j][q] = 0.f;

    const uint32_t sAh = smem_u32(Ah), sAl = smem_u32(Al);
    const uint32_t sBh = smem_u32(Bh), sBl = smem_u32(Bl);

    for (int ck = 0; ck < NCH; ck++) {
#pragma unroll
        for (int i = 0; i < AITER; i++) {
            int f = tid + i * 256;
            int r = f >> 4;
            int kq = f & 15;
            int grow = rowBase + r;
            float4 v = make_float4(0.f, 0.f, 0.f, 0.f);
            if (grow < M) {
                v = *(const float4*)(A + (size_t)grow * KTOT + ck * KC + kq * 4);
                if (BN_A) {
                    const float4 sc = *(const float4*)(g_scale + ck * KC + kq * 4);
                    const float4 sh = *(const float4*)(g_shift + ck * KC + kq * 4);
                    v.x = fmaxf(fmaf(v.x, sc.x, sh.x), 0.f);
                    v.y = fmaxf(fmaf(v.y, sc.y, sh.y), 0.f);
                    v.z = fmaxf(fmaf(v.z, sc.z, sh.z), 0.f);
                    v.w = fmaxf(fmaf(v.w, sc.w, sh.w), 0.f);
                }
            }
            __nv_bfloat162 h01 = __nv_bfloat162(__float2bfloat16(v.x), __float2bfloat16(v.y));
            __nv_bfloat162 h23 = __nv_bfloat162(__float2bfloat16(v.z), __float2bfloat16(v.w));
            __nv_bfloat162 l01 = __nv_bfloat162(
                __float2bfloat16(v.x - __bfloat162float(h01.x)),
                __float2bfloat16(v.y - __bfloat162float(h01.y)));
            __nv_bfloat162 l23 = __nv_bfloat162(
                __float2bfloat16(v.z - __bfloat162float(h23.x)),
                __float2bfloat16(v.w - __bfloat162float(h23.y)));
            uint32_t o = (uint32_t)r * SA + (uint32_t)kq * 8;
            *(uint2*)(Ah + o) = make_uint2(*(uint32_t*)&h01, *(uint32_t*)&h23);
            *(uint2*)(Al + o) = make_uint2(*(uint32_t*)&l01, *(uint32_t*)&l23);
        }
#pragma unroll
        for (int i = 0; i < 4; i++) {
            int f = tid + i * 256;
            int r = f >> 3;
            int g = f & 7;
            size_t si = (size_t)(colBase + r) * KTOT + ck * KC + g * 8;
            uint32_t o = (uint32_t)r * SA + (uint32_t)g * 16;
            *(uint4*)(Bh + o) = *(const uint4*)(Bhi + si);
            *(uint4*)(Bl + o) = *(const uint4*)(Blo + si);
        }
        __syncthreads();

#pragma unroll
        for (int pass = 0; pass < 3; pass++) {
            const uint32_t sa = (pass == 2) ? sAl : sAh;
            const uint32_t sb = (pass == 1) ? sBl : sBh;
#pragma unroll
            for (int ks = 0; ks < KC / 16; ks++) {
                const int k0 = ks * 16;
                uint32_t af[2][4];
#pragma unroll
                for (int mt = 0; mt < 2; mt++) {
                    int row = warpM * 32 + mt * 16 + (lane & 15);
                    uint32_t addr = sa + (uint32_t)row * SA +
                                    (uint32_t)(k0 + ((lane >> 4) << 3)) * 2;
                    LDSM_X4(af[mt], addr);
                }
                uint32_t bf[NT16][4];
#pragma unroll
                for (int nt = 0; nt < NT16; nt++) {
                    int nrow = warpN * WN + nt * 16 + ((lane >> 4) << 3) + (lane & 7);
                    uint32_t addr = sb + (uint32_t)nrow * SA +
                                    (uint32_t)(k0 + (((lane >> 3) & 1) << 3)) * 2;
                    LDSM_X4(bf[nt], addr);
                }
#pragma unroll
                for (int mt = 0; mt < 2; mt++)
#pragma unroll
                    for (int j = 0; j < N8; j++)
                        mma16816(acc[mt][j], af[mt],
                                 bf[j >> 1][(j & 1) * 2], bf[j >> 1][(j & 1) * 2 + 1]);
            }
        }
        __syncthreads();
    }

    // ---- epilogue (+ optional bias) ----
#pragma unroll
    for (int mt = 0; mt < 2; mt++) {
        int r0 = rowBase + warpM * 32 + mt * 16 + (lane >> 2);
#pragma unroll
        for (int j = 0; j < N8; j++) {
            int col = colBase + warpN * WN + j * 8 + (lane & 3) * 2;
            float b0 = 0.f, b1v = 0.f;
            if (BIASF) { b0 = __ldg(bias + col); b1v = __ldg(bias + col + 1); }
            if (r0 < M)
                *(float2*)(C + (size_t)r0 * NTOT + col) =
                    make_float2(acc[mt][j][0] + b0, acc[mt][j][1] + b1v);
            if (r0 + 8 < M)
                *(float2*)(C + (size_t)(r0 + 8) * NTOT + col) =
                    make_float2(acc[mt][j][2] + b0, acc[mt][j][3] + b1v);
        }
    }
}

// ---------------- BN stats over y1 (linear streaming read, L2-hot) ----------------
__global__ __launch_bounds__(HID_CH) void k_bnstats(int M) {
    const int c = threadIdx.x;
    const int rows = (M + gridDim.x - 1) / gridDim.x;
    const int r0 = blockIdx.x * rows;
    const int r1 = min(r0 + rows, M);
    float sum = 0.f, sq = 0.f;
    for (int r = r0; r < r1; r++) {
        float v = g_y1[(size_t)r * HID_CH + c];
        sum += v;
        sq  = fmaf(v, v, sq);
    }
    atomicAdd(&g_bnsum[c], sum);
    atomicAdd(&g_bnsq[c],  sq);
}

__global__ void k_bn_finalize(const float* __restrict__ gamma,
                              const float* __restrict__ beta, int M) {
    int c = threadIdx.x;
    if (c >= HID_CH) return;
    float inv = 1.0f / (float)M;
    float mu  = g_bnsum[c] * inv;
    float var = g_bnsq[c] * inv - mu * mu;
    float rs  = rsqrtf(var + BN_EPS);
    float sc  = gamma[c] * rs;
    g_scale[c] = sc;
    g_shift[c] = beta[c] - mu * sc;
}

// ---------------- launch ----------------
extern "C" void kernel_launch(void* const* d_in, const int* in_sizes, int n_in,
                              void* d_out, int out_size) {
    const float* x      = (const float*)d_in[0];
    const int*   ei     = (const int*)  d_in[1];
    const float* W1     = (const float*)d_in[2];
    const float* b1     = (const float*)d_in[3];
    const float* gamma1 = (const float*)d_in[4];
    const float* beta1  = (const float*)d_in[5];
    const float* W2     = (const float*)d_in[6];
    const float* b2     = (const float*)d_in[7];
    float* out = (float*)d_out;

    const int M = in_sizes[0] / IN_CH;    // 50000
    const int E = in_sizes[1] / 2;        // 800000
    const int* src = ei;
    const int* dst = ei + E;

    float *py1, *pzx;
    cudaGetSymbolAddress((void**)&py1, g_y1);
    cudaGetSymbolAddress((void**)&pzx, g_zx);
    __nv_bfloat16 *pw1h, *pw1l, *pw2h, *pw2l;
    cudaGetSymbolAddress((void**)&pw1h, g_wt1hi);
    cudaGetSymbolAddress((void**)&pw1l, g_wt1lo);
    cudaGetSymbolAddress((void**)&pw2h, g_wt2hi);
    cudaGetSymbolAddress((void**)&pw2l, g_wt2lo);

    const int SM1 = (128 + 128 + 128 + 128) * SA;  // BM=128: 73728 B
    const int SM2 = (64 + 64 + 128 + 128) * SA;    // BM=64:  55296 B
    cudaFuncSetAttribute(k_mma_gemm<false, true, IN_CH, HID_CH, 128>,
                         cudaFuncAttributeMaxDynamicSharedMemorySize, SM1);
    cudaFuncSetAttribute(k_mma_gemm<true, false, HID_CH, OUT_CH, 64>,
                         cudaFuncAttributeMaxDynamicSharedMemorySize, SM2);

    const int NB = (M + 255) / 256;

    // CSR build + normalization + weight prep
    k_initprep<<<256, 256>>>(W1, W2, M);
    k_deg<<<(E + 255) / 256, 256>>>(dst, E);
    k_scan1<<<NB, 256>>>(M);
    k_scan2<<<1, 256>>>(NB);
    k_scan3_dis<<<(M + 255) / 256, 256>>>(M);
    k_fill<<<(E + 255) / 256, 256>>>(src, dst, E);

    // layer 1: zx = agg(x)  (128-ch gather, 4-edge unrolled)
    k_gather<false><<<592, 256>>>(x, pzx, nullptr, M, E);
    // y1 = zx @ W1 + b1
    {
        dim3 grid(HID_CH / 128, (M + 127) / 128);
        k_mma_gemm<false, true, IN_CH, HID_CH, 128><<<grid, 256, SM1>>>(
            pzx, pw1h, pw1l, b1, py1, M);
    }
    k_bnstats<<<512, HID_CH>>>(M);
    k_bn_finalize<<<1, HID_CH>>>(gamma1, beta1, M);

    // layer 2: h2 = relu(bn(y1)) @ W2  (reuses g_zx for h2)
    {
        dim3 grid(OUT_CH / 128, (M + 63) / 64);
        k_mma_gemm<true, false, HID_CH, OUT_CH, 64><<<grid, 256, SM2>>>(
            py1, pw2h, pw2l, nullptr, pzx, M);
    }
    // out = agg(h2) + b2
    k_gather<true><<<592, 256>>>(pzx, out, b2, M, E);
}

// round 11
// speedup vs baseline: 1.4104x; 1.0548x over previous
#include <cuda_runtime.h>
#include <cuda_bf16.h>
#include <cuda_fp16.h>
#include <cstddef>
#include <cstdint>

#define N_NODES_MAX 50000
#define E_MAX       800000
#define IN_CH   128
#define HID_CH  256
#define OUT_CH  128
#define BN_EPS  1e-5f
#define SA      144      // smem row stride (bytes): 64 bf16 + 16B pad

// ---------------- scratch (device globals) ----------------
__device__ float  g_y1[(size_t)N_NODES_MAX * HID_CH];  // gemm1 output
__device__ float  g_zx[(size_t)N_NODES_MAX * IN_CH];   // agg(x) fp32
__device__ __half g_half[(size_t)N_NODES_MAX * 128];   // x as fp16; later h2 as fp16
__device__ int    g_degi[N_NODES_MAX];
__device__ int    g_off[N_NODES_MAX];                  // scan; post-fill: row END offsets
__device__ int    g_esrc[E_MAX];
__device__ int    g_bsum[256];
__device__ int    g_bscan[256];
__device__ float  g_dis[N_NODES_MAX];
__device__ float  g_bnsum[HID_CH];
__device__ float  g_bnsq[HID_CH];
__device__ float  g_scale[HID_CH];
__device__ float  g_shift[HID_CH];
// W transposed + split to bf16 (K-major rows: [N][K])
__device__ __align__(16) __nv_bfloat16 g_wt1hi[HID_CH * IN_CH];   // [256,128]
__device__ __align__(16) __nv_bfloat16 g_wt1lo[HID_CH * IN_CH];
__device__ __align__(16) __nv_bfloat16 g_wt2hi[OUT_CH * HID_CH];  // [128,256]
__device__ __align__(16) __nv_bfloat16 g_wt2lo[OUT_CH * HID_CH];

__device__ __forceinline__ void fma4(float4& a, const float4 v, const float s) {
    a.x = fmaf(v.x, s, a.x);
    a.y = fmaf(v.y, s, a.y);
    a.z = fmaf(v.z, s, a.z);
    a.w = fmaf(v.w, s, a.w);
}

// load 4 fp16 channels (lane covers ch 4*lane..4*lane+3) as float4
__device__ __forceinline__ float4 ldrow_h(const __half* base, int row, int lane) {
    uint2 u = ((const uint2*)(base + (size_t)row * 128))[lane];
    float2 f0 = __half22float2(*(__half2*)&u.x);
    float2 f1 = __half22float2(*(__half2*)&u.y);
    return make_float4(f0.x, f0.y, f1.x, f1.y);
}

__device__ __forceinline__ uint32_t smem_u32(const void* p) {
    uint32_t a;
    asm("{ .reg .u64 t; cvta.to.shared.u64 t, %1; cvt.u32.u64 %0, t; }" : "=r"(a) : "l"(p));
    return a;
}

#define LDSM_X4(r, addr) \
    asm volatile("ldmatrix.sync.aligned.m8n8.x4.shared.b16 {%0,%1,%2,%3}, [%4];" \
                 : "=r"((r)[0]), "=r"((r)[1]), "=r"((r)[2]), "=r"((r)[3]) : "r"(addr))

__device__ __forceinline__ void mma16816(float* c, const uint32_t* a, uint32_t b0, uint32_t b1) {
    asm volatile(
        "mma.sync.aligned.m16n8k16.row.col.f32.bf16.bf16.f32 "
        "{%0,%1,%2,%3}, {%4,%5,%6,%7}, {%8,%9}, {%0,%1,%2,%3};"
        : "+f"(c[0]), "+f"(c[1]), "+f"(c[2]), "+f"(c[3])
        : "r"(a[0]), "r"(a[1]), "r"(a[2]), "r"(a[3]), "r"(b0), "r"(b1));
}

// ---------------- init + W transpose/split (fused) ----------------
__global__ void k_initprep(const float* __restrict__ W1, const float* __restrict__ W2, int M) {
    int i = blockIdx.x * blockDim.x + threadIdx.x;   // 65536 threads
    if (i < M) g_degi[i] = 0;
    if (i < HID_CH) { g_bnsum[i] = 0.f; g_bnsq[i] = 0.f; }
    if (i < IN_CH * HID_CH) {                 // W1 [128,256] -> WT1 [256,128]
        int k = i / HID_CH, n = i % HID_CH;
        float v = W1[i];
        __nv_bfloat16 h = __float2bfloat16(v);
        g_wt1hi[n * IN_CH + k] = h;
        g_wt1lo[n * IN_CH + k] = __float2bfloat16(v - __bfloat162float(h));
    }
    if (i < HID_CH * OUT_CH) {                // W2 [256,128] -> WT2 [128,256]
        int k = i / OUT_CH, n = i % OUT_CH;
        float v = W2[i];
        __nv_bfloat16 h = __float2bfloat16(v);
        g_wt2hi[n * HID_CH + k] = h;
        g_wt2lo[n * HID_CH + k] = __float2bfloat16(v - __bfloat162float(h));
    }
}

// ---------------- x -> fp16 conversion (vectorized streaming) ----------------
__global__ void k_x2h(const float* __restrict__ x, long total4) {
    long stride = (long)gridDim.x * blockDim.x;
    for (long i = (long)blockIdx.x * blockDim.x + threadIdx.x; i < total4; i += stride) {
        float4 v = ((const float4*)x)[i];
        uint2 u;
        *(__half2*)&u.x = __floats2half2_rn(v.x, v.y);
        *(__half2*)&u.y = __floats2half2_rn(v.z, v.w);
        ((uint2*)g_half)[i] = u;
    }
}

// ---------------- degree histogram ----------------
__global__ void k_deg(const int* __restrict__ dst, int E) {
    int i = blockIdx.x * blockDim.x + threadIdx.x;
    if (i < E) atomicAdd(&g_degi[dst[i]], 1);
}

// ---------------- exclusive scan over degrees ----------------
__global__ void k_scan1(int M) {
    __shared__ int s[256];
    int tid = threadIdx.x;
    int i = blockIdx.x * 256 + tid;
    int v = (i < M) ? g_degi[i] : 0;
    s[tid] = v;
    __syncthreads();
#pragma unroll
    for (int off = 1; off < 256; off <<= 1) {
        int t = (tid >= off) ? s[tid - off] : 0;
        __syncthreads();
        s[tid] += t;
        __syncthreads();
    }
    if (i < M) g_off[i] = s[tid] - v;
    if (tid == 255) g_bsum[blockIdx.x] = s[255];
}

__global__ void k_scan2(int NB) {
    __shared__ int s[256];
    int tid = threadIdx.x;
    int v = (tid < NB) ? g_bsum[tid] : 0;
    s[tid] = v;
    __syncthreads();
#pragma unroll
    for (int off = 1; off < 256; off <<= 1) {
        int t = (tid >= off) ? s[tid - off] : 0;
        __syncthreads();
        s[tid] += t;
        __syncthreads();
    }
    g_bscan[tid] = s[tid] - v;
}

// scan finalize + dis (fused)
__global__ void k_scan3_dis(int M) {
    int i = blockIdx.x * blockDim.x + threadIdx.x;
    if (i < M) {
        g_off[i] += g_bscan[i >> 8];
        g_dis[i] = rsqrtf((float)g_degi[i] + 1.0f);
    }
}

// ---------------- CSR fill (cursor = g_off itself; post-fill g_off[d] = row end) ----------------
__global__ void k_fill(const int* __restrict__ src, const int* __restrict__ dst, int E) {
    int i = blockIdx.x * blockDim.x + threadIdx.x;
    if (i < E) {
        int d = dst[i];
        int pos = atomicAdd(&g_off[d], 1);
        g_esrc[pos] = src[i];
    }
}

// ---------------- 128-ch fp16-input gather, 4-edge unroll + dual accumulators ----------------
// outp[d] = sum_in inp[s]*norm + inp[d]*dis^2 (+bias), fp32 accumulation / fp32 output.
// CSR rows: [d ? g_off[d-1] : 0, g_off[d])
template <bool BIAS>
__global__ __launch_bounds__(256) void k_gather_h(const __half* __restrict__ inp,
                                                  float* __restrict__ outp,
                                                  const float* __restrict__ bias,
                                                  int M, int E) {
    const int tid = threadIdx.x, lane = tid & 31, wid = tid >> 5;
    float4 bb = make_float4(0.f, 0.f, 0.f, 0.f);
    if (BIAS) bb = ((const float4*)bias)[lane];

    for (int d = blockIdx.x * 8 + wid; d < M; d += gridDim.x * 8) {
        float disd = g_dis[d];
        int beg = d ? g_off[d - 1] : 0;
        int end = g_off[d];
        float4 a  = make_float4(0.f, 0.f, 0.f, 0.f);
        float4 a2 = make_float4(0.f, 0.f, 0.f, 0.f);

        int j = beg;
        for (; j + 4 <= end; j += 4) {
            int s0 = g_esrc[j],     s1 = g_esrc[j + 1];
            int s2 = g_esrc[j + 2], s3 = g_esrc[j + 3];
            float w0 = g_dis[s0], w1 = g_dis[s1], w2 = g_dis[s2], w3 = g_dis[s3];
            float4 v0 = ldrow_h(inp, s0, lane);
            float4 v1 = ldrow_h(inp, s1, lane);
            float4 v2 = ldrow_h(inp, s2, lane);
            float4 v3 = ldrow_h(inp, s3, lane);
            fma4(a,  v0, disd * w0);
            fma4(a2, v1, disd * w1);
            fma4(a,  v2, disd * w2);
            fma4(a2, v3, disd * w3);
        }
        for (; j < end; j++) {
            int s0 = g_esrc[j];
            float w0 = disd * g_dis[s0];
            float4 v0 = ldrow_h(inp, s0, lane);
            fma4(a, v0, w0);
        }
        float self = disd * disd;
        float4 sv = ldrow_h(inp, d, lane);
        fma4(a, sv, self);
        a.x += a2.x; a.y += a2.y; a.z += a2.z; a.w += a2.w;
        if (BIAS) { a.x += bb.x; a.y += bb.y; a.z += bb.z; a.w += bb.w; }
        ((float4*)(outp + (size_t)d * 128))[lane] = a;
    }
}

// ---------------- mma.sync bf16-split GEMM ----------------
// C[M,NTOT] = op(A)[M,KTOT] @ W[KTOT,NTOT]; W pre-split: Bhi/Blo [NTOT][KTOT] bf16.
// BN_A fuses relu(a*scale+shift) into A convert; BIASF adds bias[col];
// HALF_OUT stores C as fp16 (C cast to __half*).
template <bool BN_A, bool BIASF, bool HALF_OUT, int KTOT, int NTOT, int BM>
__global__ __launch_bounds__(256, 2)
void k_mma_gemm(const float* __restrict__ A,
                const __nv_bfloat16* __restrict__ Bhi,
                const __nv_bfloat16* __restrict__ Blo,
                const float* __restrict__ bias,
                float* __restrict__ C, int M) {
    constexpr int KC = 64;
    constexpr int NCH = KTOT / KC;
    constexpr int WARPS_M = BM / 32;
    constexpr int WARPS_N = 8 / WARPS_M;
    constexpr int WN = 128 / WARPS_N;
    constexpr int NT16 = WN / 16;
    constexpr int N8 = WN / 8;
    constexpr int AITER = BM * 16 / 256;

    extern __shared__ char sm[];
    char* Ah = sm;
    char* Al = Ah + BM * SA;
    char* Bh = Al + BM * SA;
    char* Bl = Bh + 128 * SA;

    const int tid  = threadIdx.x;
    const int lane = tid & 31;
    const int wid  = tid >> 5;
    const int warpM = wid % WARPS_M;
    const int warpN = wid / WARPS_M;
    const int rowBase = blockIdx.y * BM;
    const int colBase = blockIdx.x * 128;

    float acc[2][N8][4];
#pragma unroll
    for (int i = 0; i < 2; i++)
#pragma unroll
        for (int j = 0; j < N8; j++)
#pragma unroll
            for (int q = 0; q < 4; q++) acc[i][j][q] = 0.f;

    const uint32_t sAh = smem_u32(Ah), sAl = smem_u32(Al);
    const uint32_t sBh = smem_u32(Bh), sBl = smem_u32(Bl);

    for (int ck = 0; ck < NCH; ck++) {
#pragma unroll
        for (int i = 0; i < AITER; i++) {
            int f = tid + i * 256;
            int r = f >> 4;
            int kq = f & 15;
            int grow = rowBase + r;
            float4 v = make_float4(0.f, 0.f, 0.f, 0.f);
            if (grow < M) {
                v = *(const float4*)(A + (size_t)grow * KTOT + ck * KC + kq * 4);
                if (BN_A) {
                    const float4 sc = *(const float4*)(g_scale + ck * KC + kq * 4);
                    const float4 sh = *(const float4*)(g_shift + ck * KC + kq * 4);
                    v.x = fmaxf(fmaf(v.x, sc.x, sh.x), 0.f);
                    v.y = fmaxf(fmaf(v.y, sc.y, sh.y), 0.f);
                    v.z = fmaxf(fmaf(v.z, sc.z, sh.z), 0.f);
                    v.w = fmaxf(fmaf(v.w, sc.w, sh.w), 0.f);
                }
            }
            __nv_bfloat162 h01 = __nv_bfloat162(__float2bfloat16(v.x), __float2bfloat16(v.y));
            __nv_bfloat162 h23 = __nv_bfloat162(__float2bfloat16(v.z), __float2bfloat16(v.w));
            __nv_bfloat162 l01 = __nv_bfloat162(
                __float2bfloat16(v.x - __bfloat162float(h01.x)),
                __float2bfloat16(v.y - __bfloat162float(h01.y)));
            __nv_bfloat162 l23 = __nv_bfloat162(
                __float2bfloat16(v.z - __bfloat162float(h23.x)),
                __float2bfloat16(v.w - __bfloat162float(h23.y)));
            uint32_t o = (uint32_t)r * SA + (uint32_t)kq * 8;
            *(uint2*)(Ah + o) = make_uint2(*(uint32_t*)&h01, *(uint32_t*)&h23);
            *(uint2*)(Al + o) = make_uint2(*(uint32_t*)&l01, *(uint32_t*)&l23);
        }
#pragma unroll
        for (int i = 0; i < 4; i++) {
            int f = tid + i * 256;
            int r = f >> 3;
            int g = f & 7;
            size_t si = (size_t)(colBase + r) * KTOT + ck * KC + g * 8;
            uint32_t o = (uint32_t)r * SA + (uint32_t)g * 16;
            *(uint4*)(Bh + o) = *(const uint4*)(Bhi + si);
            *(uint4*)(Bl + o) = *(const uint4*)(Blo + si);
        }
        __syncthreads();

#pragma unroll
        for (int pass = 0; pass < 3; pass++) {
            const uint32_t sa = (pass == 2) ? sAl : sAh;
            const uint32_t sb = (pass == 1) ? sBl : sBh;
#pragma unroll
            for (int ks = 0; ks < KC / 16; ks++) {
                const int k0 = ks * 16;
                uint32_t af[2][4];
#pragma unroll
                for (int mt = 0; mt < 2; mt++) {
                    int row = warpM * 32 + mt * 16 + (lane & 15);
                    uint32_t addr = sa + (uint32_t)row * SA +
                                    (uint32_t)(k0 + ((lane >> 4) << 3)) * 2;
                    LDSM_X4(af[mt], addr);
                }
                uint32_t bf[NT16][4];
#pragma unroll
                for (int nt = 0; nt < NT16; nt++) {
                    int nrow = warpN * WN + nt * 16 + ((lane >> 4) << 3) + (lane & 7);
                    uint32_t addr = sb + (uint32_t)nrow * SA +
                                    (uint32_t)(k0 + (((lane >> 3) & 1) << 3)) * 2;
                    LDSM_X4(bf[nt], addr);
                }
#pragma unroll
                for (int mt = 0; mt < 2; mt++)
#pragma unroll
                    for (int j = 0; j < N8; j++)
                        mma16816(acc[mt][j], af[mt],
                                 bf[j >> 1][(j & 1) * 2], bf[j >> 1][(j & 1) * 2 + 1]);
            }
        }
        __syncthreads();
    }

    // ---- epilogue (+ optional bias; fp32 or fp16 store) ----
#pragma unroll
    for (int mt = 0; mt < 2; mt++) {
        int r0 = rowBase + warpM * 32 + mt * 16 + (lane >> 2);
#pragma unroll
        for (int j = 0; j < N8; j++) {
            int col = colBase + warpN * WN + j * 8 + (lane & 3) * 2;
            float b0 = 0.f, b1v = 0.f;
            if (BIASF) { b0 = __ldg(bias + col); b1v = __ldg(bias + col + 1); }
            float v0 = acc[mt][j][0] + b0, v1 = acc[mt][j][1] + b1v;
            float v2 = acc[mt][j][2] + b0, v3 = acc[mt][j][3] + b1v;
            if (HALF_OUT) {
                __half* Ch = (__half*)C;
                if (r0 < M)
                    *(__half2*)(Ch + (size_t)r0 * NTOT + col) = __floats2half2_rn(v0, v1);
                if (r0 + 8 < M)
                    *(__half2*)(Ch + (size_t)(r0 + 8) * NTOT + col) = __floats2half2_rn(v2, v3);
            } else {
                if (r0 < M)
                    *(float2*)(C + (size_t)r0 * NTOT + col) = make_float2(v0, v1);
                if (r0 + 8 < M)
                    *(float2*)(C + (size_t)(r0 + 8) * NTOT + col) = make_float2(v2, v3);
            }
        }
    }
}

// ---------------- BN stats over y1 (linear streaming read, L2-hot) ----------------
__global__ __launch_bounds__(HID_CH) void k_bnstats(int M) {
    const int c = threadIdx.x;
    const int rows = (M + gridDim.x - 1) / gridDim.x;
    const int r0 = blockIdx.x * rows;
    const int r1 = min(r0 + rows, M);
    float sum = 0.f, sq = 0.f;
    for (int r = r0; r < r1; r++) {
        float v = g_y1[(size_t)r * HID_CH + c];
        sum += v;
        sq  = fmaf(v, v, sq);
    }
    atomicAdd(&g_bnsum[c], sum);
    atomicAdd(&g_bnsq[c],  sq);
}

__global__ void k_bn_finalize(const float* __restrict__ gamma,
                              const float* __restrict__ beta, int M) {
    int c = threadIdx.x;
    if (c >= HID_CH) return;
    float inv = 1.0f / (float)M;
    float mu  = g_bnsum[c] * inv;
    float var = g_bnsq[c] * inv - mu * mu;
    float rs  = rsqrtf(var + BN_EPS);
    float sc  = gamma[c] * rs;
    g_scale[c] = sc;
    g_shift[c] = beta[c] - mu * sc;
}

// ---------------- launch ----------------
extern "C" void kernel_launch(void* const* d_in, const int* in_sizes, int n_in,
                              void* d_out, int out_size) {
    const float* x      = (const float*)d_in[0];
    const int*   ei     = (const int*)  d_in[1];
    const float* W1     = (const float*)d_in[2];
    const float* b1     = (const float*)d_in[3];
    const float* gamma1 = (const float*)d_in[4];
    const float* beta1  = (const float*)d_in[5];
    const float* W2     = (const float*)d_in[6];
    const float* b2     = (const float*)d_in[7];
    float* out = (float*)d_out;

    const int M = in_sizes[0] / IN_CH;    // 50000
    const int E = in_sizes[1] / 2;        // 800000
    const int* src = ei;
    const int* dst = ei + E;

    float *py1, *pzx;
    cudaGetSymbolAddress((void**)&py1, g_y1);
    cudaGetSymbolAddress((void**)&pzx, g_zx);
    __half* phalf;
    cudaGetSymbolAddress((void**)&phalf, g_half);
    __nv_bfloat16 *pw1h, *pw1l, *pw2h, *pw2l;
    cudaGetSymbolAddress((void**)&pw1h, g_wt1hi);
    cudaGetSymbolAddress((void**)&pw1l, g_wt1lo);
    cudaGetSymbolAddress((void**)&pw2h, g_wt2hi);
    cudaGetSymbolAddress((void**)&pw2l, g_wt2lo);

    const int SM1 = (128 + 128 + 128 + 128) * SA;  // BM=128: 73728 B
    const int SM2 = (64 + 64 + 128 + 128) * SA;    // BM=64:  55296 B
    cudaFuncSetAttribute(k_mma_gemm<false, true, false, IN_CH, HID_CH, 128>,
                         cudaFuncAttributeMaxDynamicSharedMemorySize, SM1);
    cudaFuncSetAttribute(k_mma_gemm<true, false, true, HID_CH, OUT_CH, 64>,
                         cudaFuncAttributeMaxDynamicSharedMemorySize, SM2);

    const int NB = (M + 255) / 256;

    // CSR build + normalization + weight prep + x->fp16
    k_initprep<<<256, 256>>>(W1, W2, M);
    k_x2h<<<2048, 256>>>(x, (long)M * IN_CH / 4);
    k_deg<<<(E + 255) / 256, 256>>>(dst, E);
    k_scan1<<<NB, 256>>>(M);
    k_scan2<<<1, 256>>>(NB);
    k_scan3_dis<<<(M + 255) / 256, 256>>>(M);
    k_fill<<<(E + 255) / 256, 256>>>(src, dst, E);

    // layer 1: zx = agg(x_fp16)  (fp16 reads, fp32 accumulate)
    k_gather_h<false><<<592, 256>>>(phalf, pzx, nullptr, M, E);
    // y1 = zx @ W1 + b1
    {
        dim3 grid(HID_CH / 128, (M + 127) / 128);
        k_mma_gemm<false, true, false, IN_CH, HID_CH, 128><<<grid, 256, SM1>>>(
            pzx, pw1h, pw1l, b1, py1, M);
    }
    k_bnstats<<<512, HID_CH>>>(M);
    k_bn_finalize<<<1, HID_CH>>>(gamma1, beta1, M);

    // layer 2: h2 = relu(bn(y1)) @ W2 -> fp16 (reuses g_half; BN+ReLU fused)
    {
        dim3 grid(OUT_CH / 128, (M + 63) / 64);
        k_mma_gemm<true, false, true, HID_CH, OUT_CH, 64><<<grid, 256, SM2>>>(
            py1, pw2h, pw2l, nullptr, (float*)phalf, M);
    }
    // out = agg(h2_fp16) + b2
    k_gather_h<true><<<592, 256>>>(phalf, out, b2, M, E);
}

// round 12
// speedup vs baseline: 1.8691x; 1.3252x over previous
#include <cuda_runtime.h>
#include <cuda_fp16.h>
#include <cstddef>
#include <cstdint>

#define N_NODES_MAX 50000
#define E_MAX       800000
#define IN_CH   128
#define HID_CH  256
#define OUT_CH  128
#define BN_EPS  1e-5f
#define SA      144      // smem row stride (bytes): 64 fp16 + 16B pad

// ---------------- scratch (device globals) ----------------
__device__ float  g_y1[(size_t)N_NODES_MAX * HID_CH];  // gemm1 output
__device__ float  g_zx[(size_t)N_NODES_MAX * IN_CH];   // agg(x) fp32
__device__ __half g_half[(size_t)N_NODES_MAX * 128];   // x as fp16; later h2 as fp16
__device__ int    g_degi[N_NODES_MAX];
__device__ int    g_off[N_NODES_MAX];                  // scan; post-fill: row END offsets
__device__ int    g_esrc[E_MAX];
__device__ int    g_bsum[256];
__device__ int    g_bscan[256];
__device__ float  g_dis[N_NODES_MAX];
__device__ float  g_bnsum[HID_CH];
__device__ float  g_bnsq[HID_CH];
__device__ float  g_scale[HID_CH];
__device__ float  g_shift[HID_CH];
// W transposed to fp16 (K-major rows: [N][K])
__device__ __align__(16) __half g_wt1[HID_CH * IN_CH];   // [256,128]
__device__ __align__(16) __half g_wt2[OUT_CH * HID_CH];  // [128,256]

__device__ __forceinline__ void fma4(float4& a, const float4 v, const float s) {
    a.x = fmaf(v.x, s, a.x);
    a.y = fmaf(v.y, s, a.y);
    a.z = fmaf(v.z, s, a.z);
    a.w = fmaf(v.w, s, a.w);
}

// load 4 fp16 channels (lane covers ch 4*lane..4*lane+3) as float4
__device__ __forceinline__ float4 ldrow_h(const __half* base, int row, int lane) {
    uint2 u = ((const uint2*)(base + (size_t)row * 128))[lane];
    float2 f0 = __half22float2(*(__half2*)&u.x);
    float2 f1 = __half22float2(*(__half2*)&u.y);
    return make_float4(f0.x, f0.y, f1.x, f1.y);
}

__device__ __forceinline__ uint32_t smem_u32(const void* p) {
    uint32_t a;
    asm("{ .reg .u64 t; cvta.to.shared.u64 t, %1; cvt.u32.u64 %0, t; }" : "=r"(a) : "l"(p));
    return a;
}

#define LDSM_X4(r, addr) \
    asm volatile("ldmatrix.sync.aligned.m8n8.x4.shared.b16 {%0,%1,%2,%3}, [%4];" \
                 : "=r"((r)[0]), "=r"((r)[1]), "=r"((r)[2]), "=r"((r)[3]) : "r"(addr))

__device__ __forceinline__ void mma16816h(float* c, const uint32_t* a, uint32_t b0, uint32_t b1) {
    asm volatile(
        "mma.sync.aligned.m16n8k16.row.col.f32.f16.f16.f32 "
        "{%0,%1,%2,%3}, {%4,%5,%6,%7}, {%8,%9}, {%0,%1,%2,%3};"
        : "+f"(c[0]), "+f"(c[1]), "+f"(c[2]), "+f"(c[3])
        : "r"(a[0]), "r"(a[1]), "r"(a[2]), "r"(a[3]), "r"(b0), "r"(b1));
}

// ---------------- init + W transpose to fp16 (fused) ----------------
__global__ void k_initprep(const float* __restrict__ W1, const float* __restrict__ W2, int M) {
    int i = blockIdx.x * blockDim.x + threadIdx.x;   // 65536 threads
    if (i < M) g_degi[i] = 0;
    if (i < HID_CH) { g_bnsum[i] = 0.f; g_bnsq[i] = 0.f; }
    if (i < IN_CH * HID_CH) {                 // W1 [128,256] -> WT1 [256,128]
        int k = i / HID_CH, n = i % HID_CH;
        g_wt1[n * IN_CH + k] = __float2half_rn(W1[i]);
    }
    if (i < HID_CH * OUT_CH) {                // W2 [256,128] -> WT2 [128,256]
        int k = i / OUT_CH, n = i % OUT_CH;
        g_wt2[n * HID_CH + k] = __float2half_rn(W2[i]);
    }
}

// ---------------- degree histogram + x->fp16 (fused; independent ranges) ----------------
__global__ void k_deg_x2h(const int* __restrict__ dst, const float* __restrict__ x,
                          int E, long total4) {
    long i = (long)blockIdx.x * blockDim.x + threadIdx.x;
    if (i < E) atomicAdd(&g_degi[dst[i]], 1);
    if (i < total4) {
        float4 v = ((const float4*)x)[i];
        uint2 u;
        *(__half2*)&u.x = __floats2half2_rn(v.x, v.y);
        *(__half2*)&u.y = __floats2half2_rn(v.z, v.w);
        ((uint2*)g_half)[i] = u;
    }
}

// ---------------- exclusive scan over degrees ----------------
__global__ void k_scan1(int M) {
    __shared__ int s[256];
    int tid = threadIdx.x;
    int i = blockIdx.x * 256 + tid;
    int v = (i < M) ? g_degi[i] : 0;
    s[tid] = v;
    __syncthreads();
#pragma unroll
    for (int off = 1; off < 256; off <<= 1) {
        int t = (tid >= off) ? s[tid - off] : 0;
        __syncthreads();
        s[tid] += t;
        __syncthreads();
    }
    if (i < M) g_off[i] = s[tid] - v;
    if (tid == 255) g_bsum[blockIdx.x] = s[255];
}

__global__ void k_scan2(int NB) {
    __shared__ int s[256];
    int tid = threadIdx.x;
    int v = (tid < NB) ? g_bsum[tid] : 0;
    s[tid] = v;
    __syncthreads();
#pragma unroll
    for (int off = 1; off < 256; off <<= 1) {
        int t = (tid >= off) ? s[tid - off] : 0;
        __syncthreads();
        s[tid] += t;
        __syncthreads();
    }
    g_bscan[tid] = s[tid] - v;
}

// scan finalize + dis (fused)
__global__ void k_scan3_dis(int M) {
    int i = blockIdx.x * blockDim.x + threadIdx.x;
    if (i < M) {
        g_off[i] += g_bscan[i >> 8];
        g_dis[i] = rsqrtf((float)g_degi[i] + 1.0f);
    }
}

// ---------------- CSR fill (cursor = g_off itself; post-fill g_off[d] = row end) ----------------
__global__ void k_fill(const int* __restrict__ src, const int* __restrict__ dst, int E) {
    int i = blockIdx.x * blockDim.x + threadIdx.x;
    if (i < E) {
        int d = dst[i];
        int pos = atomicAdd(&g_off[d], 1);
        g_esrc[pos] = src[i];
    }
}

// ---------------- 128-ch fp16-input gather, 4-edge unroll + dual accumulators ----------------
// outp[d] = sum_in inp[s]*norm + inp[d]*dis^2 (+bias), fp32 accumulation / fp32 output.
// CSR rows: [d ? g_off[d-1] : 0, g_off[d])
template <bool BIAS>
__global__ __launch_bounds__(256) void k_gather_h(const __half* __restrict__ inp,
                                                  float* __restrict__ outp,
                                                  const float* __restrict__ bias,
                                                  int M, int E) {
    const int tid = threadIdx.x, lane = tid & 31, wid = tid >> 5;
    float4 bb = make_float4(0.f, 0.f, 0.f, 0.f);
    if (BIAS) bb = ((const float4*)bias)[lane];

    for (int d = blockIdx.x * 8 + wid; d < M; d += gridDim.x * 8) {
        float disd = g_dis[d];
        int beg = d ? g_off[d - 1] : 0;
        int end = g_off[d];
        float4 a  = make_float4(0.f, 0.f, 0.f, 0.f);
        float4 a2 = make_float4(0.f, 0.f, 0.f, 0.f);

        int j = beg;
        for (; j + 4 <= end; j += 4) {
            int s0 = g_esrc[j],     s1 = g_esrc[j + 1];
            int s2 = g_esrc[j + 2], s3 = g_esrc[j + 3];
            float w0 = g_dis[s0], w1 = g_dis[s1], w2 = g_dis[s2], w3 = g_dis[s3];
            float4 v0 = ldrow_h(inp, s0, lane);
            float4 v1 = ldrow_h(inp, s1, lane);
            float4 v2 = ldrow_h(inp, s2, lane);
            float4 v3 = ldrow_h(inp, s3, lane);
            fma4(a,  v0, disd * w0);
            fma4(a2, v1, disd * w1);
            fma4(a,  v2, disd * w2);
            fma4(a2, v3, disd * w3);
        }
        for (; j < end; j++) {
            int s0 = g_esrc[j];
            float w0 = disd * g_dis[s0];
            float4 v0 = ldrow_h(inp, s0, lane);
            fma4(a, v0, w0);
        }
        float self = disd * disd;
        float4 sv = ldrow_h(inp, d, lane);
        fma4(a, sv, self);
        a.x += a2.x; a.y += a2.y; a.z += a2.z; a.w += a2.w;
        if (BIAS) { a.x += bb.x; a.y += bb.y; a.z += bb.z; a.w += bb.w; }
        ((float4*)(outp + (size_t)d * 128))[lane] = a;
    }
}

// ---------------- mma.sync single-pass fp16 GEMM ----------------
// C[M,NTOT] = op(A)[M,KTOT] @ W[KTOT,NTOT]; W pre-transposed fp16 [NTOT][KTOT].
// BN_A fuses relu(a*scale+shift) into A convert; BIASF adds bias[col];
// HALF_OUT stores C as fp16 (C cast to __half*).
template <bool BN_A, bool BIASF, bool HALF_OUT, int KTOT, int NTOT, int BM>
__global__ __launch_bounds__(256, 2)
void k_mma_gemm(const float* __restrict__ A,
                const __half* __restrict__ B,
                const float* __restrict__ bias,
                float* __restrict__ C, int M) {
    constexpr int KC = 64;
    constexpr int NCH = KTOT / KC;
    constexpr int WARPS_M = BM / 32;
    constexpr int WARPS_N = 8 / WARPS_M;
    constexpr int WN = 128 / WARPS_N;
    constexpr int NT16 = WN / 16;
    constexpr int N8 = WN / 8;
    constexpr int AITER = BM * 16 / 256;

    extern __shared__ char sm[];
    char* Ah = sm;
    char* Bh = Ah + BM * SA;

    const int tid  = threadIdx.x;
    const int lane = tid & 31;
    const int wid  = tid >> 5;
    const int warpM = wid % WARPS_M;
    const int warpN = wid / WARPS_M;
    const int rowBase = blockIdx.y * BM;
    const int colBase = blockIdx.x * 128;

    float acc[2][N8][4];
#pragma unroll
    for (int i = 0; i < 2; i++)
#pragma unroll
        for (int j = 0; j < N8; j++)
#pragma unroll
            for (int q = 0; q < 4; q++) acc[i][j][q] = 0.f;

    const uint32_t sAh = smem_u32(Ah);
    const uint32_t sBh = smem_u32(Bh);

    for (int ck = 0; ck < NCH; ck++) {
        // ---- A: BM rows x 64 k fp32 -> fp16 in smem ----
#pragma unroll
        for (int i = 0; i < AITER; i++) {
            int f = tid + i * 256;
            int r = f >> 4;
            int kq = f & 15;
            int grow = rowBase + r;
            float4 v = make_float4(0.f, 0.f, 0.f, 0.f);
            if (grow < M) {
                v = *(const float4*)(A + (size_t)grow * KTOT + ck * KC + kq * 4);
                if (BN_A) {
                    const float4 sc = *(const float4*)(g_scale + ck * KC + kq * 4);
                    const float4 sh = *(const float4*)(g_shift + ck * KC + kq * 4);
                    v.x = fmaxf(fmaf(v.x, sc.x, sh.x), 0.f);
                    v.y = fmaxf(fmaf(v.y, sc.y, sh.y), 0.f);
                    v.z = fmaxf(fmaf(v.z, sc.z, sh.z), 0.f);
                    v.w = fmaxf(fmaf(v.w, sc.w, sh.w), 0.f);
                }
            }
            uint2 u;
            *(__half2*)&u.x = __floats2half2_rn(v.x, v.y);
            *(__half2*)&u.y = __floats2half2_rn(v.z, v.w);
            *(uint2*)(Ah + (uint32_t)r * SA + (uint32_t)kq * 8) = u;
        }
        // ---- B: 128 rows(N) x 64 k fp16 copy ----
#pragma unroll
        for (int i = 0; i < 4; i++) {
            int f = tid + i * 256;
            int r = f >> 3;
            int g = f & 7;
            size_t si = (size_t)(colBase + r) * KTOT + ck * KC + g * 8;
            *(uint4*)(Bh + (uint32_t)r * SA + (uint32_t)g * 16) = *(const uint4*)(B + si);
        }
        __syncthreads();

#pragma unroll
        for (int ks = 0; ks < KC / 16; ks++) {
            const int k0 = ks * 16;
            uint32_t af[2][4];
#pragma unroll
            for (int mt = 0; mt < 2; mt++) {
                int row = warpM * 32 + mt * 16 + (lane & 15);
                uint32_t addr = sAh + (uint32_t)row * SA +
                                (uint32_t)(k0 + ((lane >> 4) << 3)) * 2;
                LDSM_X4(af[mt], addr);
            }
            uint32_t bf[NT16][4];
#pragma unroll
            for (int nt = 0; nt < NT16; nt++) {
                int nrow = warpN * WN + nt * 16 + ((lane >> 4) << 3) + (lane & 7);
                uint32_t addr = sBh + (uint32_t)nrow * SA +
                                (uint32_t)(k0 + (((lane >> 3) & 1) << 3)) * 2;
                LDSM_X4(bf[nt], addr);
            }
#pragma unroll
            for (int mt = 0; mt < 2; mt++)
#pragma unroll
                for (int j = 0; j < N8; j++)
                    mma16816h(acc[mt][j], af[mt],
                              bf[j >> 1][(j & 1) * 2], bf[j >> 1][(j & 1) * 2 + 1]);
        }
        __syncthreads();
    }

    // ---- epilogue (+ optional bias; fp32 or fp16 store) ----
#pragma unroll
    for (int mt = 0; mt < 2; mt++) {
        int r0 = rowBase + warpM * 32 + mt * 16 + (lane >> 2);
#pragma unroll
        for (int j = 0; j < N8; j++) {
            int col = colBase + warpN * WN + j * 8 + (lane & 3) * 2;
            float b0 = 0.f, b1v = 0.f;
            if (BIASF) { b0 = __ldg(bias + col); b1v = __ldg(bias + col + 1); }
            float v0 = acc[mt][j][0] + b0, v1 = acc[mt][j][1] + b1v;
            float v2 = acc[mt][j][2] + b0, v3 = acc[mt][j][3] + b1v;
            if (HALF_OUT) {
                __half* Ch = (__half*)C;
                if (r0 < M)
                    *(__half2*)(Ch + (size_t)r0 * NTOT + col) = __floats2half2_rn(v0, v1);
                if (r0 + 8 < M)
                    *(__half2*)(Ch + (size_t)(r0 + 8) * NTOT + col) = __floats2half2_rn(v2, v3);
            } else {
                if (r0 < M)
                    *(float2*)(C + (size_t)r0 * NTOT + col) = make_float2(v0, v1);
                if (r0 + 8 < M)
                    *(float2*)(C + (size_t)(r0 + 8) * NTOT + col) = make_float2(v2, v3);
            }
        }
    }
}

// ---------------- BN stats over y1 (linear streaming read, L2-hot) ----------------
__global__ __launch_bounds__(HID_CH) void k_bnstats(int M) {
    const int c = threadIdx.x;
    const int rows = (M + gridDim.x - 1) / gridDim.x;
    const int r0 = blockIdx.x * rows;
    const int r1 = min(r0 + rows, M);
    float sum = 0.f, sq = 0.f;
    for (int r = r0; r < r1; r++) {
        float v = g_y1[(size_t)r * HID_CH + c];
        sum += v;
        sq  = fmaf(v, v, sq);
    }
    atomicAdd(&g_bnsum[c], sum);
    atomicAdd(&g_bnsq[c],  sq);
}

__global__ void k_bn_finalize(const float* __restrict__ gamma,
                              const float* __restrict__ beta, int M) {
    int c = threadIdx.x;
    if (c >= HID_CH) return;
    float inv = 1.0f / (float)M;
    float mu  = g_bnsum[c] * inv;
    float var = g_bnsq[c] * inv - mu * mu;
    float rs  = rsqrtf(var + BN_EPS);
    float sc  = gamma[c] * rs;
    g_scale[c] = sc;
    g_shift[c] = beta[c] - mu * sc;
}

// ---------------- launch ----------------
extern "C" void kernel_launch(void* const* d_in, const int* in_sizes, int n_in,
                              void* d_out, int out_size) {
    const float* x      = (const float*)d_in[0];
    const int*   ei     = (const int*)  d_in[1];
    const float* W1     = (const float*)d_in[2];
    const float* b1     = (const float*)d_in[3];
    const float* gamma1 = (const float*)d_in[4];
    const float* beta1  = (const float*)d_in[5];
    const float* W2     = (const float*)d_in[6];
    const float* b2     = (const float*)d_in[7];
    float* out = (float*)d_out;

    const int M = in_sizes[0] / IN_CH;    // 50000
    const int E = in_sizes[1] / 2;        // 800000
    const int* src = ei;
    const int* dst = ei + E;

    float *py1, *pzx;
    cudaGetSymbolAddress((void**)&py1, g_y1);
    cudaGetSymbolAddress((void**)&pzx, g_zx);
    __half* phalf;
    cudaGetSymbolAddress((void**)&phalf, g_half);
    __half *pw1, *pw2;
    cudaGetSymbolAddress((void**)&pw1, g_wt1);
    cudaGetSymbolAddress((void**)&pw2, g_wt2);

    const int SM1 = (128 + 128) * SA;  // BM=128: 36864 B
    const int SM2 = (64 + 128) * SA;   // BM=64:  27648 B
    cudaFuncSetAttribute(k_mma_gemm<false, true, false, IN_CH, HID_CH, 128>,
                         cudaFuncAttributeMaxDynamicSharedMemorySize, SM1);
    cudaFuncSetAttribute(k_mma_gemm<true, false, true, HID_CH, OUT_CH, 64>,
                         cudaFuncAttributeMaxDynamicSharedMemorySize, SM2);

    const int NB = (M + 255) / 256;
    const long total4 = (long)M * IN_CH / 4;

    // CSR build + normalization + weight prep + x->fp16
    k_initprep<<<256, 256>>>(W1, W2, M);
    k_deg_x2h<<<(int)((total4 + 255) / 256), 256>>>(dst, x, E, total4);
    k_scan1<<<NB, 256>>>(M);
    k_scan2<<<1, 256>>>(NB);
    k_scan3_dis<<<(M + 255) / 256, 256>>>(M);
    k_fill<<<(E + 255) / 256, 256>>>(src, dst, E);

    // layer 1: zx = agg(x_fp16)
    k_gather_h<false><<<592, 256>>>(phalf, pzx, nullptr, M, E);
    // y1 = zx @ W1 + b1  (single-pass fp16 MMA)
    {
        dim3 grid(HID_CH / 128, (M + 127) / 128);
        k_mma_gemm<false, true, false, IN_CH, HID_CH, 128><<<grid, 256, SM1>>>(
            pzx, pw1, b1, py1, M);
    }
    k_bnstats<<<512, HID_CH>>>(M);
    k_bn_finalize<<<1, HID_CH>>>(gamma1, beta1, M);

    // layer 2: h2 = relu(bn(y1)) @ W2 -> fp16 (reuses g_half; BN+ReLU fused)
    {
        dim3 grid(OUT_CH / 128, (M + 63) / 64);
        k_mma_gemm<true, false, true, HID_CH, OUT_CH, 64><<<grid, 256, SM2>>>(
            py1, pw2, nullptr, (float*)phalf, M);
    }
    // out = agg(h2_fp16) + b2
    k_gather_h<true><<<592, 256>>>(phalf, out, b2, M, E);
}